// round 2
// baseline (speedup 1.0000x reference)
#include <cuda_runtime.h>
#include <cuda_bf16.h>
#include <cstdint>

// Problem constants
#define S_DIM   512
#define B_DIM   128
#define N_OBJ   64
#define D_MODEL 512
#define H_DIM   1024   // 2*d
#define SB      (S_DIM * B_DIM)     // 65536
#define NB      (N_OBJ * B_DIM)     // 8192

// ---------------- device scratch (no allocations allowed) ----------------
__device__ float g_TQ[8 * H_DIM];            // type_emb @ W1[0:512]
__device__ float g_DW[8 * H_DIM];            // dir_emb  @ W1[1536:2048]
__device__ float g_QW[(size_t)NB * H_DIM];   // obj_e @ W1[512:1024]
__device__ float g_RW[(size_t)NB * H_DIM];   // obj_e @ W1[1024:1536]
__device__ float g_h [(size_t)SB * H_DIM];   // relu(x@W1 + b1), 256 MB
__device__ int   g_is64;                     // constraints stored as int64?
__device__ int   g_mask32;                   // mask stored as int32?

// ---------------- dtype detection ---------------------------------------
// constraints: values in [0,6). If int64, high 32-bit word of every element
// is 0. If int32, odd words are random small ints (nonzero w.p. 5/6 each).
// mask: values 0/1. If int32, bytes at idx%4 != 0 are all zero. If bool/u8,
// those bytes are other mask entries, ~50% nonzero each (96 samples).
__global__ void detect_kernel(const unsigned int* __restrict__ cw,
                              const unsigned char* __restrict__ mk) {
    unsigned int v = cw[2 * threadIdx.x + 1];
    unsigned int any_c = __ballot_sync(0xffffffffu, v != 0u);
    unsigned char mb = (unsigned char)(mk[4 * threadIdx.x + 1] |
                                       mk[4 * threadIdx.x + 2] |
                                       mk[4 * threadIdx.x + 3]);
    unsigned int any_m = __ballot_sync(0xffffffffu, mb != 0);
    if (threadIdx.x == 0) {
        g_is64   = (any_c == 0u) ? 1 : 0;
        g_mask32 = (any_m == 0u) ? 1 : 0;
    }
}

// ---------------- tiny GEMM: TQ and DW --------------------------------
// 16 blocks (8 type rows + 8 dir rows), 256 threads, each thread 4 outputs.
__global__ void emb_kernel(const float* __restrict__ type_emb,
                           const float* __restrict__ dir_emb,
                           const float* __restrict__ W1) {
    __shared__ float se[D_MODEL];
    int bid = blockIdx.x;
    const float* e   = (bid < 8) ? (type_emb + bid * D_MODEL)
                                 : (dir_emb + (bid - 8) * D_MODEL);
    const float* W   = (bid < 8) ? W1 : (W1 + (size_t)1536 * H_DIM);
    float* out       = (bid < 8) ? (g_TQ + bid * H_DIM)
                                 : (g_DW + (bid - 8) * H_DIM);
    int tid = threadIdx.x;
    se[tid]       = e[tid];
    se[tid + 256] = e[tid + 256];
    __syncthreads();
    float a0 = 0.f, a1 = 0.f, a2 = 0.f, a3 = 0.f;
    for (int i = 0; i < D_MODEL; i++) {
        float ev = se[i];
        const float* wr = W + (size_t)i * H_DIM + tid;
        a0 = fmaf(ev, wr[0],   a0);
        a1 = fmaf(ev, wr[256], a1);
        a2 = fmaf(ev, wr[512], a2);
        a3 = fmaf(ev, wr[768], a3);
    }
    out[tid] = a0; out[tid + 256] = a1; out[tid + 512] = a2; out[tid + 768] = a3;
}

// ---------------- tiled fp32 SGEMM -------------------------------------
// C[M,N] = A[M,K] @ B[K,N] (+bias). BM=128, BN=64, BK=16, 256 threads,
// 8x4 micro-tile per thread. All dims divide tiles exactly for this problem.
#define BM 128
#define BN 64
#define BK 16
#define TM 8
#define TN 4

__global__ __launch_bounds__(256) void sgemm_kernel(
    const float* __restrict__ A, int lda,
    const float* __restrict__ B, int ldb,
    float* __restrict__ C, int ldc,
    int K, const float* __restrict__ bias)
{
    __shared__ float As[BK][BM];   // transposed: [k][m]
    __shared__ float Bs[BK][BN];

    const int tid = threadIdx.x;
    const int bm  = blockIdx.y * BM;
    const int bn  = blockIdx.x * BN;
    const int tx  = tid & 15;   // 0..15  (N dir)
    const int ty  = tid >> 4;   // 0..15  (M dir)

    float acc[TM][TN];
#pragma unroll
    for (int i = 0; i < TM; i++)
#pragma unroll
        for (int j = 0; j < TN; j++) acc[i][j] = 0.f;

    // A load mapping: 128x16 tile = 512 float4; thread loads 2 float4.
    const int a_row = tid >> 2;          // 0..63
    const int a_col = (tid & 3) * 4;     // 0,4,8,12
    // B load mapping: 16x64 tile = 256 float4; thread loads 1 float4.
    const int b_row = tid >> 4;          // 0..15
    const int b_col = (tid & 15) * 4;    // 0..60

    for (int k0 = 0; k0 < K; k0 += BK) {
#pragma unroll
        for (int r = 0; r < 2; r++) {
            int row = a_row + r * 64;
            float4 v = *(const float4*)&A[(size_t)(bm + row) * lda + k0 + a_col];
            As[a_col + 0][row] = v.x;
            As[a_col + 1][row] = v.y;
            As[a_col + 2][row] = v.z;
            As[a_col + 3][row] = v.w;
        }
        {
            float4 v = *(const float4*)&B[(size_t)(k0 + b_row) * ldb + bn + b_col];
            *(float4*)&Bs[b_row][b_col] = v;
        }
        __syncthreads();

#pragma unroll
        for (int kk = 0; kk < BK; kk++) {
            float a[TM], bf[TN];
            float4 a0 = *(const float4*)&As[kk][ty * TM];
            float4 a1 = *(const float4*)&As[kk][ty * TM + 4];
            a[0]=a0.x; a[1]=a0.y; a[2]=a0.z; a[3]=a0.w;
            a[4]=a1.x; a[5]=a1.y; a[6]=a1.z; a[7]=a1.w;
            float4 b0 = *(const float4*)&Bs[kk][tx * TN];
            bf[0]=b0.x; bf[1]=b0.y; bf[2]=b0.z; bf[3]=b0.w;
#pragma unroll
            for (int i = 0; i < TM; i++)
#pragma unroll
                for (int j = 0; j < TN; j++)
                    acc[i][j] = fmaf(a[i], bf[j], acc[i][j]);
        }
        __syncthreads();
    }

    float4 bv = make_float4(0.f, 0.f, 0.f, 0.f);
    if (bias) bv = *(const float4*)&bias[bn + tx * TN];
#pragma unroll
    for (int i = 0; i < TM; i++) {
        int row = bm + ty * TM + i;
        float4 o;
        o.x = acc[i][0] + bv.x;
        o.y = acc[i][1] + bv.y;
        o.z = acc[i][2] + bv.z;
        o.w = acc[i][3] + bv.w;
        *(float4*)&C[(size_t)row * ldc + bn + tx * TN] = o;
    }
}

// ---------------- build h = relu(gathered sums + b1) --------------------
// One block per (s,b) row; 256 threads x float4 covers 1024 dims.
__global__ __launch_bounds__(256) void build_h_kernel(
    const unsigned int* __restrict__ cons,   // constraints words
    const unsigned char* __restrict__ mask,  // (B,S), bool or int32
    const float* __restrict__ b1)
{
    const int row = blockIdx.x;            // s*128 + b
    const int b   = row & 127;
    const int s   = row >> 7;

    int t, q, r, dd;
    size_t base = (size_t)row * 4;
    if (g_is64) {
        t  = (int)cons[(base + 0) * 2];
        q  = (int)cons[(base + 1) * 2];
        r  = (int)cons[(base + 2) * 2];
        dd = (int)cons[(base + 3) * 2];
    } else {
        t  = (int)cons[base + 0];
        q  = (int)cons[base + 1];
        r  = (int)cons[base + 2];
        dd = (int)cons[base + 3];
    }
    bool pad;
    if (g_mask32) {
        pad = ((const int*)mask)[(size_t)b * S_DIM + s] != 0;
    } else {
        pad = mask[(size_t)b * S_DIM + s] != 0;
    }
    const bool se     = (t == 4) || (t == 5);
    const bool orient = (t == 2) || (t == 3);
    const float ft = pad ? 0.f : 1.f;
    const float fq = (pad || se) ? 0.f : 1.f;
    const float fd = (pad || se || orient) ? 0.f : 1.f;

    const float4* tq = (const float4*)(g_TQ + (size_t)t * H_DIM);
    const float4* qw = (const float4*)(g_QW + (size_t)(q * B_DIM + b) * H_DIM);
    const float4* rw = (const float4*)(g_RW + (size_t)(r * B_DIM + b) * H_DIM);
    const float4* dw = (const float4*)(g_DW + (size_t)dd * H_DIM);
    const float4* bb = (const float4*)b1;
    float4* out = (float4*)(g_h + (size_t)row * H_DIM);

    int i = threadIdx.x;
    float4 A = tq[i], Q = qw[i], R = rw[i], D = dw[i], Bv = bb[i];
    float4 o;
    o.x = fmaxf(ft * A.x + fq * (Q.x + R.x) + fd * D.x + Bv.x, 0.f);
    o.y = fmaxf(ft * A.y + fq * (Q.y + R.y) + fd * D.y + Bv.y, 0.f);
    o.z = fmaxf(ft * A.z + fq * (Q.z + R.z) + fd * D.z + Bv.z, 0.f);
    o.w = fmaxf(ft * A.w + fq * (Q.w + R.w) + fd * D.w + Bv.w, 0.f);
    out[i] = o;
}

// ---------------- launch ------------------------------------------------
extern "C" void kernel_launch(void* const* d_in, const int* in_sizes, int n_in,
                              void* d_out, int out_size) {
    const unsigned int*  constraints = (const unsigned int*)d_in[0];
    const unsigned char* mask        = (const unsigned char*)d_in[1];
    const float* obj_e    = (const float*)d_in[2];   // (64,128,512)
    const float* type_emb = (const float*)d_in[3];   // (8,512)
    const float* dir_emb  = (const float*)d_in[4];   // (8,512)
    const float* W1       = (const float*)d_in[5];   // (2048,1024)
    const float* b1       = (const float*)d_in[6];   // (1024)
    const float* W2       = (const float*)d_in[7];   // (1024,512)
    const float* b2       = (const float*)d_in[8];   // (512)
    float* out = (float*)d_out;                      // (512,128,512)

    // resolve scratch pointers
    float *pQW, *pRW, *pH;
    cudaGetSymbolAddress((void**)&pQW, g_QW);
    cudaGetSymbolAddress((void**)&pRW, g_RW);
    cudaGetSymbolAddress((void**)&pH,  g_h);

    // 0) dtype detection (constraints int64/int32, mask bool/int32)
    detect_kernel<<<1, 32>>>(constraints, mask);

    // 1) TQ / DW (tiny)
    emb_kernel<<<16, 256>>>(type_emb, dir_emb, W1);

    // 2) QW = obj_e @ W1[512:1024], RW = obj_e @ W1[1024:1536]
    {
        dim3 grid(H_DIM / BN, NB / BM);   // (16, 64)
        sgemm_kernel<<<grid, 256>>>(obj_e, D_MODEL,
                                    W1 + (size_t)512 * H_DIM, H_DIM,
                                    pQW, H_DIM, D_MODEL, nullptr);
        sgemm_kernel<<<grid, 256>>>(obj_e, D_MODEL,
                                    W1 + (size_t)1024 * H_DIM, H_DIM,
                                    pRW, H_DIM, D_MODEL, nullptr);
    }

    // 3) h = relu(TQ[t] + QW[q,b] + RW[r,b] + DW[d] + b1) with masks
    build_h_kernel<<<SB, 256>>>(constraints, mask, b1);

    // 4) out = h @ W2 + b2
    {
        dim3 grid(512 / BN, SB / BM);     // (8, 512)
        sgemm_kernel<<<grid, 256>>>(pH, H_DIM, W2, 512, out, 512, H_DIM, b2);
    }
}

// round 4
// speedup vs baseline: 2.5587x; 2.5587x over previous
#include <cuda_runtime.h>
#include <cuda_bf16.h>
#include <cstdint>

// ---------------- problem constants ----------------
#define S_DIM   512
#define B_DIM   128
#define N_OBJ   64
#define D_MODEL 512
#define H_DIM   1024
#define SB      (S_DIM * B_DIM)     // 65536
#define NB      (N_OBJ * B_DIM)     // 8192

// ---------------- device scratch ----------------
__device__ float g_TQ[8 * H_DIM];
__device__ float g_DW[8 * H_DIM];
__device__ float g_QR[(size_t)NB * 2048];                  // [8192,2048] = QW|RW
__device__ __nv_bfloat16 g_obj_hi[(size_t)NB * D_MODEL];
__device__ __nv_bfloat16 g_obj_lo[(size_t)NB * D_MODEL];
__device__ __nv_bfloat16 g_W1t_hi[(size_t)2048 * D_MODEL]; // [n=2048,k=512]
__device__ __nv_bfloat16 g_W1t_lo[(size_t)2048 * D_MODEL];
__device__ __nv_bfloat16 g_W2t_hi[(size_t)512 * H_DIM];    // [n=512,k=1024]
__device__ __nv_bfloat16 g_W2t_lo[(size_t)512 * H_DIM];
__device__ __nv_bfloat16 g_hhi[(size_t)SB * H_DIM];
__device__ __nv_bfloat16 g_hlo[(size_t)SB * H_DIM];
__device__ int g_is64, g_mask32;

// ---------------- PTX helpers (sm_80+ portable) ----------------
__device__ __forceinline__ uint32_t smem_u32(const void* p) {
    uint32_t a;
    asm("{ .reg .u64 t; cvta.to.shared.u64 t, %1; cvt.u32.u64 %0, t; }"
        : "=r"(a) : "l"(p));
    return a;
}
__device__ __forceinline__ void cp16(uint32_t dst, const void* src) {
    asm volatile("cp.async.cg.shared.global [%0], [%1], 16;"
                 :: "r"(dst), "l"(src));
}
#define CP_COMMIT() asm volatile("cp.async.commit_group;" ::: "memory")
#define CP_WAIT(n)  asm volatile("cp.async.wait_group %0;" :: "n"(n) : "memory")

__device__ __forceinline__ void ldsm_x4(uint32_t* r, uint32_t addr) {
    asm volatile("ldmatrix.sync.aligned.m8n8.x4.shared.b16 {%0,%1,%2,%3}, [%4];"
                 : "=r"(r[0]), "=r"(r[1]), "=r"(r[2]), "=r"(r[3]) : "r"(addr));
}
__device__ __forceinline__ void mma16816(float* c, const uint32_t* a,
                                         uint32_t b0, uint32_t b1) {
    asm volatile(
        "mma.sync.aligned.m16n8k16.row.col.f32.bf16.bf16.f32 "
        "{%0,%1,%2,%3}, {%4,%5,%6,%7}, {%8,%9}, {%0,%1,%2,%3};"
        : "+f"(c[0]), "+f"(c[1]), "+f"(c[2]), "+f"(c[3])
        : "r"(a[0]), "r"(a[1]), "r"(a[2]), "r"(a[3]), "r"(b0), "r"(b1));
}

// ---------------- dtype detection ----------------
__global__ void detect_kernel(const unsigned int* __restrict__ cw,
                              const unsigned char* __restrict__ mk) {
    unsigned int v = cw[2 * threadIdx.x + 1];
    unsigned int any_c = __ballot_sync(0xffffffffu, v != 0u);
    unsigned char mb = (unsigned char)(mk[4 * threadIdx.x + 1] |
                                       mk[4 * threadIdx.x + 2] |
                                       mk[4 * threadIdx.x + 3]);
    unsigned int any_m = __ballot_sync(0xffffffffu, mb != 0);
    if (threadIdx.x == 0) {
        g_is64   = (any_c == 0u) ? 1 : 0;
        g_mask32 = (any_m == 0u) ? 1 : 0;
    }
}

// ---------------- tiny GEMM: TQ and DW (fp32 exact) ----------------
__global__ void emb_kernel(const float* __restrict__ type_emb,
                           const float* __restrict__ dir_emb,
                           const float* __restrict__ W1) {
    __shared__ float se[D_MODEL];
    int bid = blockIdx.x;
    const float* e = (bid < 8) ? (type_emb + bid * D_MODEL)
                               : (dir_emb + (bid - 8) * D_MODEL);
    const float* W = (bid < 8) ? W1 : (W1 + (size_t)1536 * H_DIM);
    float* out = (bid < 8) ? (g_TQ + bid * H_DIM) : (g_DW + (bid - 8) * H_DIM);
    int tid = threadIdx.x;
    se[tid] = e[tid]; se[tid + 256] = e[tid + 256];
    __syncthreads();
    float a0 = 0.f, a1 = 0.f, a2 = 0.f, a3 = 0.f;
    for (int i = 0; i < D_MODEL; i++) {
        float ev = se[i];
        const float* wr = W + (size_t)i * H_DIM + tid;
        a0 = fmaf(ev, wr[0], a0); a1 = fmaf(ev, wr[256], a1);
        a2 = fmaf(ev, wr[512], a2); a3 = fmaf(ev, wr[768], a3);
    }
    out[tid] = a0; out[tid+256] = a1; out[tid+512] = a2; out[tid+768] = a3;
}

// ---------------- fp32 -> bf16 hi/lo splits ----------------
__device__ __forceinline__ void split1(float v, __nv_bfloat16& h, __nv_bfloat16& l) {
    h = __float2bfloat16(v);
    l = __float2bfloat16(v - __bfloat162float(h));
}

__global__ void split_obj_kernel(const float* __restrict__ src) {
    size_t i = (size_t)blockIdx.x * 256 + threadIdx.x;
    __nv_bfloat16 h, l;
    split1(src[i], h, l);
    g_obj_hi[i] = h; g_obj_lo[i] = l;
}

__global__ void w1t_kernel(const float* __restrict__ W1) {
    int idx = blockIdx.x * 256 + threadIdx.x;   // 2048*512
    int n = idx >> 9;
    int k = idx & 511;
    int col = n & 1023;
    int row = ((n < 1024) ? 512 : 1024) + k;
    float v = W1[(size_t)row * H_DIM + col];
    __nv_bfloat16 h, l; split1(v, h, l);
    g_W1t_hi[idx] = h; g_W1t_lo[idx] = l;
}

__global__ void w2t_kernel(const float* __restrict__ W2) {
    int idx = blockIdx.x * 256 + threadIdx.x;   // 512*1024
    int n = idx >> 10;
    int k = idx & 1023;
    float v = W2[(size_t)k * 512 + n];
    __nv_bfloat16 h, l; split1(v, h, l);
    g_W2t_hi[idx] = h; g_W2t_lo[idx] = l;
}

// ---------------- build h (bf16 hi/lo) ----------------
__global__ __launch_bounds__(256) void build_h_kernel(
    const unsigned int* __restrict__ cons,
    const unsigned char* __restrict__ mask,
    const float* __restrict__ b1)
{
    const int row = blockIdx.x;
    const int b = row & 127;
    const int s = row >> 7;

    int t, q, r, dd;
    size_t base = (size_t)row * 4;
    if (g_is64) {
        t  = (int)cons[(base + 0) * 2]; q  = (int)cons[(base + 1) * 2];
        r  = (int)cons[(base + 2) * 2]; dd = (int)cons[(base + 3) * 2];
    } else {
        t = (int)cons[base]; q = (int)cons[base + 1];
        r = (int)cons[base + 2]; dd = (int)cons[base + 3];
    }
    bool pad = g_mask32 ? (((const int*)mask)[(size_t)b * S_DIM + s] != 0)
                        : (mask[(size_t)b * S_DIM + s] != 0);
    const bool se = (t == 4) || (t == 5);
    const bool orient = (t == 2) || (t == 3);
    const float ft = pad ? 0.f : 1.f;
    const float fq = (pad || se) ? 0.f : 1.f;
    const float fd = (pad || se || orient) ? 0.f : 1.f;

    int i = threadIdx.x;
    const float4 A  = ((const float4*)(g_TQ + (size_t)t * H_DIM))[i];
    const float4 Q  = ((const float4*)(g_QR + (size_t)(q * B_DIM + b) * 2048))[i];
    const float4 R  = ((const float4*)(g_QR + (size_t)(r * B_DIM + b) * 2048 + 1024))[i];
    const float4 D  = ((const float4*)(g_DW + (size_t)dd * H_DIM))[i];
    const float4 Bv = ((const float4*)b1)[i];

    float o0 = fmaxf(ft * A.x + fq * (Q.x + R.x) + fd * D.x + Bv.x, 0.f);
    float o1 = fmaxf(ft * A.y + fq * (Q.y + R.y) + fd * D.y + Bv.y, 0.f);
    float o2 = fmaxf(ft * A.z + fq * (Q.z + R.z) + fd * D.z + Bv.z, 0.f);
    float o3 = fmaxf(ft * A.w + fq * (Q.w + R.w) + fd * D.w + Bv.w, 0.f);

    __nv_bfloat16 h0,l0,h1,l1,h2,l2,h3,l3;
    split1(o0,h0,l0); split1(o1,h1,l1); split1(o2,h2,l2); split1(o3,h3,l3);
    __nv_bfloat162* ph = (__nv_bfloat162*)(g_hhi + (size_t)row * H_DIM);
    __nv_bfloat162* pl = (__nv_bfloat162*)(g_hlo + (size_t)row * H_DIM);
    ph[2*i]   = __nv_bfloat162(h0, h1);
    ph[2*i+1] = __nv_bfloat162(h2, h3);
    pl[2*i]   = __nv_bfloat162(l0, l1);
    pl[2*i+1] = __nv_bfloat162(l2, l3);
}

// ---------------- split-bf16 HMMA GEMM ----------------
// C[M,N] = (Ah+Al)[M,K] @ (Bh+Bl)[N,K]^T  (3-term: AhBh + AhBl + AlBh),
// fp32 accumulate in registers. CTA tile 128x128, 8 warps of 64x32, BK=32,
// cp.async double buffering. SMEM rows: 32 bf16 = 64B = 4 x 16B units,
// swizzle u' = u ^ ((row>>1)&3)  (conflict-free for stores + ldmatrix).
#define STAGE_BYTES 32768   // Ah 8K | Al 8K | Bh 8K | Bl 8K

__device__ __forceinline__ void load_chunk(
    uint32_t sm, const __nv_bfloat16* Ah, const __nv_bfloat16* Al,
    const __nv_bfloat16* Bh, const __nv_bfloat16* Bl,
    int m0, int n0, int k0, int K, int tid)
{
#pragma unroll
    for (int i = 0; i < 2; i++) {
        int u_lin = tid + i * 256;          // 0..511
        int m = u_lin >> 2, u = u_lin & 3;
        int up = u ^ ((m >> 1) & 3);
        uint32_t d = sm + m * 64 + up * 16;
        size_t ga = (size_t)(m0 + m) * K + k0 + u * 8;
        size_t gb = (size_t)(n0 + m) * K + k0 + u * 8;
        cp16(d,          Ah + ga);
        cp16(d + 8192,   Al + ga);
        cp16(d + 16384,  Bh + gb);
        cp16(d + 24576,  Bl + gb);
    }
}

__global__ __launch_bounds__(256, 2) void mma_gemm_kernel(
    const __nv_bfloat16* __restrict__ Ah, const __nv_bfloat16* __restrict__ Al,
    const __nv_bfloat16* __restrict__ Bh, const __nv_bfloat16* __restrict__ Bl,
    const float* __restrict__ bias, float* __restrict__ C,
    int K, int ldc)
{
    extern __shared__ char smem[];
    const uint32_t sb = smem_u32(smem);
    const int tid = threadIdx.x;
    const int wid = tid >> 5, lid = tid & 31;
    const int m0 = blockIdx.y * 128;
    const int n0 = blockIdx.x * 128;
    const int wm0 = (wid & 1) * 64;     // warp M offset in tile
    const int wn0 = (wid >> 1) * 32;    // warp N offset in tile

    float acc[4][4][4];
#pragma unroll
    for (int i = 0; i < 4; i++)
#pragma unroll
        for (int j = 0; j < 4; j++)
#pragma unroll
            for (int k = 0; k < 4; k++) acc[i][j][k] = 0.f;

    // precompute per-lane ldmatrix row/unit components
    const int a_r = (lid & 15);            // A row within m16 tile
    const int a_u = (lid >> 4);            // A unit offset (0/1)
    const int b_r = (lid & 7) + ((lid >> 4) << 3);  // B row within n16 group
    const int b_u = ((lid >> 3) & 1);      // B unit offset

    const int nch = K >> 5;
    load_chunk(sb, Ah, Al, Bh, Bl, m0, n0, 0, K, tid);
    CP_COMMIT();

    for (int ch = 0; ch < nch; ch++) {
        const uint32_t stage = sb + (ch & 1) * STAGE_BYTES;
        if (ch + 1 < nch) {
            load_chunk(sb + ((ch + 1) & 1) * STAGE_BYTES,
                       Ah, Al, Bh, Bl, m0, n0, (ch + 1) * 32, K, tid);
            CP_COMMIT();
            CP_WAIT(1);
        } else {
            CP_WAIT(0);
        }
        __syncthreads();

        // three split combos: (A off, B off)
        const uint32_t combos[3][2] = {{0u, 16384u}, {0u, 24576u}, {8192u, 16384u}};
#pragma unroll
        for (int cb = 0; cb < 3; cb++) {
            const uint32_t aOff = combos[cb][0], bOff = combos[cb][1];
#pragma unroll
            for (int ks = 0; ks < 2; ks++) {
                uint32_t bfr[2][4];
#pragma unroll
                for (int bh = 0; bh < 2; bh++) {
                    int n = wn0 + bh * 16 + b_r;
                    int u = ks * 2 + b_u;
                    int up = u ^ ((n >> 1) & 3);
                    ldsm_x4(bfr[bh], stage + bOff + n * 64 + up * 16);
                }
#pragma unroll
                for (int mt = 0; mt < 4; mt++) {
                    uint32_t af[4];
                    int m = wm0 + mt * 16 + a_r;
                    int u = ks * 2 + a_u;
                    int up = u ^ ((m >> 1) & 3);
                    ldsm_x4(af, stage + aOff + m * 64 + up * 16);
#pragma unroll
                    for (int nt = 0; nt < 4; nt++) {
                        mma16816(acc[mt][nt], af,
                                 bfr[nt >> 1][(nt & 1) * 2],
                                 bfr[nt >> 1][(nt & 1) * 2 + 1]);
                    }
                }
            }
        }
        __syncthreads();
    }

    // ---- epilogue: register frags -> global (float2 per fragment row)
    const int gr = lid >> 2;
    const int gc = (lid & 3) * 2;
#pragma unroll
    for (int nt = 0; nt < 4; nt++) {
        int col = n0 + wn0 + nt * 8 + gc;
        float bx = 0.f, by = 0.f;
        if (bias) { bx = bias[col]; by = bias[col + 1]; }
#pragma unroll
        for (int mt = 0; mt < 4; mt++) {
            int row = m0 + wm0 + mt * 16 + gr;
            float2 v0 = make_float2(acc[mt][nt][0] + bx, acc[mt][nt][1] + by);
            float2 v1 = make_float2(acc[mt][nt][2] + bx, acc[mt][nt][3] + by);
            *(float2*)&C[(size_t)row * ldc + col] = v0;
            *(float2*)&C[(size_t)(row + 8) * ldc + col] = v1;
        }
    }
}

// ---------------- launch ----------------
extern "C" void kernel_launch(void* const* d_in, const int* in_sizes, int n_in,
                              void* d_out, int out_size) {
    const unsigned int*  constraints = (const unsigned int*)d_in[0];
    const unsigned char* mask        = (const unsigned char*)d_in[1];
    const float* obj_e    = (const float*)d_in[2];
    const float* type_emb = (const float*)d_in[3];
    const float* dir_emb  = (const float*)d_in[4];
    const float* W1       = (const float*)d_in[5];
    const float* b1       = (const float*)d_in[6];
    const float* W2       = (const float*)d_in[7];
    const float* b2       = (const float*)d_in[8];
    float* out = (float*)d_out;

    float* pQR;
    __nv_bfloat16 *pOH, *pOL, *pW1H, *pW1L, *pW2H, *pW2L, *pHH, *pHL;
    cudaGetSymbolAddress((void**)&pQR,  g_QR);
    cudaGetSymbolAddress((void**)&pOH,  g_obj_hi);
    cudaGetSymbolAddress((void**)&pOL,  g_obj_lo);
    cudaGetSymbolAddress((void**)&pW1H, g_W1t_hi);
    cudaGetSymbolAddress((void**)&pW1L, g_W1t_lo);
    cudaGetSymbolAddress((void**)&pW2H, g_W2t_hi);
    cudaGetSymbolAddress((void**)&pW2L, g_W2t_lo);
    cudaGetSymbolAddress((void**)&pHH,  g_hhi);
    cudaGetSymbolAddress((void**)&pHL,  g_hlo);

    const int SM_TOTAL = 2 * STAGE_BYTES;   // 64 KB
    cudaFuncSetAttribute(mma_gemm_kernel,
                         cudaFuncAttributeMaxDynamicSharedMemorySize, SM_TOTAL);

    // 0) dtype detection
    detect_kernel<<<1, 32>>>(constraints, mask);
    // 1) TQ / DW (fp32 exact, tiny)
    emb_kernel<<<16, 256>>>(type_emb, dir_emb, W1);
    // 2) bf16 splits
    split_obj_kernel<<<(NB * D_MODEL) / 256, 256>>>(obj_e);
    w1t_kernel<<<(2048 * 512) / 256, 256>>>(W1);
    w2t_kernel<<<(512 * 1024) / 256, 256>>>(W2);
    // 3) QR = obj_e @ [W1_q | W1_r]   (HMMA, M=8192 N=2048 K=512)
    {
        dim3 grid(2048 / 128, NB / 128);   // (16, 64)
        mma_gemm_kernel<<<grid, 256, SM_TOTAL>>>(pOH, pOL, pW1H, pW1L,
                                                 nullptr, pQR, D_MODEL, 2048);
    }
    // 4) h = relu(gather-sum + b1) -> bf16 hi/lo
    build_h_kernel<<<SB, 256>>>(constraints, mask, b1);
    // 5) out = h @ W2 + b2            (HMMA, M=65536 N=512 K=1024)
    {
        dim3 grid(512 / 128, SB / 128);    // (4, 512)
        mma_gemm_kernel<<<grid, 256, SM_TOTAL>>>(pHH, pHL, pW2H, pW2L,
                                                 b2, out, H_DIM, 512);
    }
}

// round 5
// speedup vs baseline: 2.7489x; 1.0743x over previous
#include <cuda_runtime.h>
#include <cuda_bf16.h>
#include <cstdint>

// ---------------- problem constants ----------------
#define S_DIM   512
#define B_DIM   128
#define N_OBJ   64
#define D_MODEL 512
#define H_DIM   1024
#define SB      (S_DIM * B_DIM)     // 65536
#define NB      (N_OBJ * B_DIM)     // 8192

// ---------------- device scratch ----------------
__device__ float g_TQ[8 * H_DIM];
__device__ float g_DW[8 * H_DIM];
__device__ float g_QR[(size_t)NB * 2048];                  // [8192,2048] = QW|RW
__device__ __nv_bfloat16 g_obj_hi[(size_t)NB * D_MODEL];
__device__ __nv_bfloat16 g_obj_lo[(size_t)NB * D_MODEL];
__device__ __nv_bfloat16 g_W1t_hi[(size_t)2048 * D_MODEL]; // [n=2048,k=512]
__device__ __nv_bfloat16 g_W1t_lo[(size_t)2048 * D_MODEL];
__device__ __nv_bfloat16 g_W2t_hi[(size_t)512 * H_DIM];    // [n=512,k=1024]
__device__ __nv_bfloat16 g_W2t_lo[(size_t)512 * H_DIM];
__device__ __nv_bfloat16 g_hhi[(size_t)SB * H_DIM];
__device__ __nv_bfloat16 g_hlo[(size_t)SB * H_DIM];
__device__ int g_is64, g_mask32;

// ---------------- PTX helpers (sm_80+ portable) ----------------
__device__ __forceinline__ uint32_t smem_u32(const void* p) {
    uint32_t a;
    asm("{ .reg .u64 t; cvta.to.shared.u64 t, %1; cvt.u32.u64 %0, t; }"
        : "=r"(a) : "l"(p));
    return a;
}
__device__ __forceinline__ void cp16(uint32_t dst, const void* src) {
    asm volatile("cp.async.cg.shared.global [%0], [%1], 16;"
                 :: "r"(dst), "l"(src));
}
#define CP_COMMIT() asm volatile("cp.async.commit_group;" ::: "memory")
#define CP_WAIT(n)  asm volatile("cp.async.wait_group %0;" :: "n"(n) : "memory")

__device__ __forceinline__ void ldsm_x4(uint32_t* r, uint32_t addr) {
    asm volatile("ldmatrix.sync.aligned.m8n8.x4.shared.b16 {%0,%1,%2,%3}, [%4];"
                 : "=r"(r[0]), "=r"(r[1]), "=r"(r[2]), "=r"(r[3]) : "r"(addr));
}
__device__ __forceinline__ void mma16816(float* c, const uint32_t* a,
                                         uint32_t b0, uint32_t b1) {
    asm volatile(
        "mma.sync.aligned.m16n8k16.row.col.f32.bf16.bf16.f32 "
        "{%0,%1,%2,%3}, {%4,%5,%6,%7}, {%8,%9}, {%0,%1,%2,%3};"
        : "+f"(c[0]), "+f"(c[1]), "+f"(c[2]), "+f"(c[3])
        : "r"(a[0]), "r"(a[1]), "r"(a[2]), "r"(a[3]), "r"(b0), "r"(b1));
}

// ---------------- dtype detection ----------------
__global__ void detect_kernel(const unsigned int* __restrict__ cw,
                              const unsigned char* __restrict__ mk) {
    unsigned int v = cw[2 * threadIdx.x + 1];
    unsigned int any_c = __ballot_sync(0xffffffffu, v != 0u);
    unsigned char mb = (unsigned char)(mk[4 * threadIdx.x + 1] |
                                       mk[4 * threadIdx.x + 2] |
                                       mk[4 * threadIdx.x + 3]);
    unsigned int any_m = __ballot_sync(0xffffffffu, mb != 0);
    if (threadIdx.x == 0) {
        g_is64   = (any_c == 0u) ? 1 : 0;
        g_mask32 = (any_m == 0u) ? 1 : 0;
    }
}

// ---------------- tiny GEMM: TQ and DW (fp32 exact) ----------------
__global__ void emb_kernel(const float* __restrict__ type_emb,
                           const float* __restrict__ dir_emb,
                           const float* __restrict__ W1) {
    __shared__ float se[D_MODEL];
    int bid = blockIdx.x;
    const float* e = (bid < 8) ? (type_emb + bid * D_MODEL)
                               : (dir_emb + (bid - 8) * D_MODEL);
    const float* W = (bid < 8) ? W1 : (W1 + (size_t)1536 * H_DIM);
    float* out = (bid < 8) ? (g_TQ + bid * H_DIM) : (g_DW + (bid - 8) * H_DIM);
    int tid = threadIdx.x;
    se[tid] = e[tid]; se[tid + 256] = e[tid + 256];
    __syncthreads();
    float a0 = 0.f, a1 = 0.f, a2 = 0.f, a3 = 0.f;
    for (int i = 0; i < D_MODEL; i++) {
        float ev = se[i];
        const float* wr = W + (size_t)i * H_DIM + tid;
        a0 = fmaf(ev, wr[0], a0); a1 = fmaf(ev, wr[256], a1);
        a2 = fmaf(ev, wr[512], a2); a3 = fmaf(ev, wr[768], a3);
    }
    out[tid] = a0; out[tid+256] = a1; out[tid+512] = a2; out[tid+768] = a3;
}

// ---------------- fp32 -> bf16 hi/lo splits ----------------
__device__ __forceinline__ void split1(float v, __nv_bfloat16& h, __nv_bfloat16& l) {
    h = __float2bfloat16(v);
    l = __float2bfloat16(v - __bfloat162float(h));
}

__global__ void split_obj_kernel(const float* __restrict__ src) {
    size_t i = (size_t)blockIdx.x * 256 + threadIdx.x;
    __nv_bfloat16 h, l;
    split1(src[i], h, l);
    g_obj_hi[i] = h; g_obj_lo[i] = l;
}

__global__ void w1t_kernel(const float* __restrict__ W1) {
    int idx = blockIdx.x * 256 + threadIdx.x;   // 2048*512
    int n = idx >> 9;
    int k = idx & 511;
    int col = n & 1023;
    int row = ((n < 1024) ? 512 : 1024) + k;
    float v = W1[(size_t)row * H_DIM + col];
    __nv_bfloat16 h, l; split1(v, h, l);
    g_W1t_hi[idx] = h; g_W1t_lo[idx] = l;
}

__global__ void w2t_kernel(const float* __restrict__ W2) {
    int idx = blockIdx.x * 256 + threadIdx.x;   // 512*1024
    int n = idx >> 10;
    int k = idx & 1023;
    float v = W2[(size_t)k * 512 + n];
    __nv_bfloat16 h, l; split1(v, h, l);
    g_W2t_hi[idx] = h; g_W2t_lo[idx] = l;
}

// ---------------- build h (bf16 hi/lo) ----------------
__global__ __launch_bounds__(256) void build_h_kernel(
    const unsigned int* __restrict__ cons,
    const unsigned char* __restrict__ mask,
    const float* __restrict__ b1)
{
    const int row = blockIdx.x;
    const int b = row & 127;
    const int s = row >> 7;

    int t, q, r, dd;
    size_t base = (size_t)row * 4;
    if (g_is64) {
        t  = (int)cons[(base + 0) * 2]; q  = (int)cons[(base + 1) * 2];
        r  = (int)cons[(base + 2) * 2]; dd = (int)cons[(base + 3) * 2];
    } else {
        t = (int)cons[base]; q = (int)cons[base + 1];
        r = (int)cons[base + 2]; dd = (int)cons[base + 3];
    }
    bool pad = g_mask32 ? (((const int*)mask)[(size_t)b * S_DIM + s] != 0)
                        : (mask[(size_t)b * S_DIM + s] != 0);
    const bool se = (t == 4) || (t == 5);
    const bool orient = (t == 2) || (t == 3);
    const float ft = pad ? 0.f : 1.f;
    const float fq = (pad || se) ? 0.f : 1.f;
    const float fd = (pad || se || orient) ? 0.f : 1.f;

    int i = threadIdx.x;
    const float4 A  = ((const float4*)(g_TQ + (size_t)t * H_DIM))[i];
    const float4 Q  = ((const float4*)(g_QR + (size_t)(q * B_DIM + b) * 2048))[i];
    const float4 R  = ((const float4*)(g_QR + (size_t)(r * B_DIM + b) * 2048 + 1024))[i];
    const float4 D  = ((const float4*)(g_DW + (size_t)dd * H_DIM))[i];
    const float4 Bv = ((const float4*)b1)[i];

    float o0 = fmaxf(ft * A.x + fq * (Q.x + R.x) + fd * D.x + Bv.x, 0.f);
    float o1 = fmaxf(ft * A.y + fq * (Q.y + R.y) + fd * D.y + Bv.y, 0.f);
    float o2 = fmaxf(ft * A.z + fq * (Q.z + R.z) + fd * D.z + Bv.z, 0.f);
    float o3 = fmaxf(ft * A.w + fq * (Q.w + R.w) + fd * D.w + Bv.w, 0.f);

    __nv_bfloat16 h0,l0,h1,l1,h2,l2,h3,l3;
    split1(o0,h0,l0); split1(o1,h1,l1); split1(o2,h2,l2); split1(o3,h3,l3);
    __nv_bfloat162* ph = (__nv_bfloat162*)(g_hhi + (size_t)row * H_DIM);
    __nv_bfloat162* pl = (__nv_bfloat162*)(g_hlo + (size_t)row * H_DIM);
    ph[2*i]   = __nv_bfloat162(h0, h1);
    ph[2*i+1] = __nv_bfloat162(h2, h3);
    pl[2*i]   = __nv_bfloat162(l0, l1);
    pl[2*i+1] = __nv_bfloat162(l2, l3);
}

// ---------------- split-bf16 HMMA GEMM (v2) ----------------
// C[M,N] = (Ah+Al)[M,K] @ (Bh+Bl)[N,K]^T  (3-term), fp32 reg accumulators.
// CTA tile 128x128, 4 warps of 64x64, BK=32, 3-stage cp.async pipeline,
// fragments register-cached across the 3 split combos.
// SMEM rows: 32 bf16 = 64B = 4 x 16B units, swizzle u' = u ^ ((row>>1)&3).
#define STAGE_BYTES 32768   // Ah 8K | Al 8K | Bh 8K | Bl 8K
#define NSTAGE 3

__device__ __forceinline__ void load_chunk(
    uint32_t sm, const __nv_bfloat16* Ah, const __nv_bfloat16* Al,
    const __nv_bfloat16* Bh, const __nv_bfloat16* Bl,
    int m0, int n0, int k0, int K, int tid)
{
#pragma unroll
    for (int i = 0; i < 4; i++) {
        int u_lin = tid + i * 128;          // 0..511
        int m = u_lin >> 2, u = u_lin & 3;
        int up = u ^ ((m >> 1) & 3);
        uint32_t d = sm + m * 64 + up * 16;
        size_t ga = (size_t)(m0 + m) * K + k0 + u * 8;
        size_t gb = (size_t)(n0 + m) * K + k0 + u * 8;
        cp16(d,          Ah + ga);
        cp16(d + 8192,   Al + ga);
        cp16(d + 16384,  Bh + gb);
        cp16(d + 24576,  Bl + gb);
    }
}

__global__ __launch_bounds__(128, 2) void mma_gemm_kernel(
    const __nv_bfloat16* __restrict__ Ah, const __nv_bfloat16* __restrict__ Al,
    const __nv_bfloat16* __restrict__ Bh, const __nv_bfloat16* __restrict__ Bl,
    const float* __restrict__ bias, float* __restrict__ C,
    int K, int ldc)
{
    extern __shared__ char smem[];
    const uint32_t sb = smem_u32(smem);
    const int tid = threadIdx.x;
    const int wid = tid >> 5, lid = tid & 31;
    const int m0 = blockIdx.y * 128;
    const int n0 = blockIdx.x * 128;
    const int wm0 = (wid & 1) * 64;     // warp M offset in tile
    const int wn0 = (wid >> 1) * 64;    // warp N offset in tile

    float acc[4][8][4];
#pragma unroll
    for (int i = 0; i < 4; i++)
#pragma unroll
        for (int j = 0; j < 8; j++)
#pragma unroll
            for (int k = 0; k < 4; k++) acc[i][j][k] = 0.f;

    // per-lane ldmatrix row/unit components (validated in R4)
    const int a_r = (lid & 15);
    const int a_u = (lid >> 4);
    const int b_r = (lid & 7) + ((lid >> 4) << 3);
    const int b_u = ((lid >> 3) & 1);

    const int nch = K >> 5;
    load_chunk(sb, Ah, Al, Bh, Bl, m0, n0, 0, K, tid);
    CP_COMMIT();
    load_chunk(sb + STAGE_BYTES, Ah, Al, Bh, Bl, m0, n0, 32, K, tid);
    CP_COMMIT();

    for (int ch = 0; ch < nch; ch++) {
        if (ch + 1 < nch) { CP_WAIT(1); } else { CP_WAIT(0); }
        __syncthreads();
        const uint32_t stage = sb + (ch % NSTAGE) * STAGE_BYTES;

#pragma unroll
        for (int ks = 0; ks < 2; ks++) {
            // ---- load B fragments once (hi+lo), reuse across combos
            uint32_t bh[4][4], bl[4][4];
#pragma unroll
            for (int bi = 0; bi < 4; bi++) {
                int n = wn0 + bi * 16 + b_r;
                int u = ks * 2 + b_u;
                int up = u ^ ((n >> 1) & 3);
                ldsm_x4(bh[bi], stage + 16384u + n * 64 + up * 16);
                ldsm_x4(bl[bi], stage + 24576u + n * 64 + up * 16);
            }
#pragma unroll
            for (int mt = 0; mt < 4; mt++) {
                uint32_t ah[4], al[4];
                int m = wm0 + mt * 16 + a_r;
                int u = ks * 2 + a_u;
                int up = u ^ ((m >> 1) & 3);
                ldsm_x4(ah, stage + m * 64 + up * 16);
                ldsm_x4(al, stage + 8192u + m * 64 + up * 16);
#pragma unroll
                for (int nt = 0; nt < 8; nt++) {
                    uint32_t bh0 = bh[nt >> 1][(nt & 1) * 2];
                    uint32_t bh1 = bh[nt >> 1][(nt & 1) * 2 + 1];
                    uint32_t bl0 = bl[nt >> 1][(nt & 1) * 2];
                    uint32_t bl1 = bl[nt >> 1][(nt & 1) * 2 + 1];
                    mma16816(acc[mt][nt], ah, bh0, bh1);   // Ah*Bh
                    mma16816(acc[mt][nt], ah, bl0, bl1);   // Ah*Bl
                    mma16816(acc[mt][nt], al, bh0, bh1);   // Al*Bh
                }
            }
        }
        // prefetch chunk ch+2 into stage (ch+2)%3 (consumed at iter ch-1; safe)
        if (ch + 2 < nch) {
            load_chunk(sb + ((ch + 2) % NSTAGE) * STAGE_BYTES,
                       Ah, Al, Bh, Bl, m0, n0, (ch + 2) * 32, K, tid);
            CP_COMMIT();
        }
    }

    // ---- epilogue: register frags -> global
    const int gr = lid >> 2;
    const int gc = (lid & 3) * 2;
#pragma unroll
    for (int nt = 0; nt < 8; nt++) {
        int col = n0 + wn0 + nt * 8 + gc;
        float bx = 0.f, by = 0.f;
        if (bias) { bx = bias[col]; by = bias[col + 1]; }
#pragma unroll
        for (int mt = 0; mt < 4; mt++) {
            int row = m0 + wm0 + mt * 16 + gr;
            float2 v0 = make_float2(acc[mt][nt][0] + bx, acc[mt][nt][1] + by);
            float2 v1 = make_float2(acc[mt][nt][2] + bx, acc[mt][nt][3] + by);
            *(float2*)&C[(size_t)row * ldc + col] = v0;
            *(float2*)&C[(size_t)(row + 8) * ldc + col] = v1;
        }
    }
}

// ---------------- launch ----------------
extern "C" void kernel_launch(void* const* d_in, const int* in_sizes, int n_in,
                              void* d_out, int out_size) {
    const unsigned int*  constraints = (const unsigned int*)d_in[0];
    const unsigned char* mask        = (const unsigned char*)d_in[1];
    const float* obj_e    = (const float*)d_in[2];
    const float* type_emb = (const float*)d_in[3];
    const float* dir_emb  = (const float*)d_in[4];
    const float* W1       = (const float*)d_in[5];
    const float* b1       = (const float*)d_in[6];
    const float* W2       = (const float*)d_in[7];
    const float* b2       = (const float*)d_in[8];
    float* out = (float*)d_out;

    float* pQR;
    __nv_bfloat16 *pOH, *pOL, *pW1H, *pW1L, *pW2H, *pW2L, *pHH, *pHL;
    cudaGetSymbolAddress((void**)&pQR,  g_QR);
    cudaGetSymbolAddress((void**)&pOH,  g_obj_hi);
    cudaGetSymbolAddress((void**)&pOL,  g_obj_lo);
    cudaGetSymbolAddress((void**)&pW1H, g_W1t_hi);
    cudaGetSymbolAddress((void**)&pW1L, g_W1t_lo);
    cudaGetSymbolAddress((void**)&pW2H, g_W2t_hi);
    cudaGetSymbolAddress((void**)&pW2L, g_W2t_lo);
    cudaGetSymbolAddress((void**)&pHH,  g_hhi);
    cudaGetSymbolAddress((void**)&pHL,  g_hlo);

    const int SM_TOTAL = NSTAGE * STAGE_BYTES;   // 96 KB
    cudaFuncSetAttribute(mma_gemm_kernel,
                         cudaFuncAttributeMaxDynamicSharedMemorySize, SM_TOTAL);

    // 0) dtype detection
    detect_kernel<<<1, 32>>>(constraints, mask);
    // 1) TQ / DW (fp32 exact, tiny)
    emb_kernel<<<16, 256>>>(type_emb, dir_emb, W1);
    // 2) bf16 splits
    split_obj_kernel<<<(NB * D_MODEL) / 256, 256>>>(obj_e);
    w1t_kernel<<<(2048 * 512) / 256, 256>>>(W1);
    w2t_kernel<<<(512 * 1024) / 256, 256>>>(W2);
    // 3) QR = obj_e @ [W1_q | W1_r]   (HMMA, M=8192 N=2048 K=512)
    {
        dim3 grid(2048 / 128, NB / 128);   // (16, 64)
        mma_gemm_kernel<<<grid, 128, SM_TOTAL>>>(pOH, pOL, pW1H, pW1L,
                                                 nullptr, pQR, D_MODEL, 2048);
    }
    // 4) h = relu(gather-sum + b1) -> bf16 hi/lo
    build_h_kernel<<<SB, 256>>>(constraints, mask, b1);
    // 5) out = h @ W2 + b2            (HMMA, M=65536 N=512 K=1024)
    {
        dim3 grid(512 / 128, SB / 128);    // (4, 512)
        mma_gemm_kernel<<<grid, 128, SM_TOTAL>>>(pHH, pHL, pW2H, pW2L,
                                                 b2, out, H_DIM, 512);
    }
}

// round 6
// speedup vs baseline: 3.2860x; 1.1954x over previous
#include <cuda_runtime.h>
#include <cuda_bf16.h>
#include <cuda_fp16.h>
#include <cstdint>

// ---------------- problem constants ----------------
#define S_DIM   512
#define B_DIM   128
#define N_OBJ   64
#define D_MODEL 512
#define H_DIM   1024
#define SB      (S_DIM * B_DIM)     // 65536
#define NB      (N_OBJ * B_DIM)     // 8192

// weight pre-scales (keep fp16 lo-parts out of subnormal range)
#define W1_SCALE 64.0f
#define W2_SCALE 32.0f

// ---------------- device scratch ----------------
__device__ float g_TQ[8 * H_DIM];
__device__ float g_DW[8 * H_DIM];
__device__ float g_QR[(size_t)NB * 2048];            // scaled by W1_SCALE
__device__ __half g_objH[(size_t)NB * D_MODEL];
__device__ __half g_objL[(size_t)NB * D_MODEL];
__device__ __half g_W1H[(size_t)2048 * D_MODEL];     // [n=2048,k=512], x64
__device__ __half g_W1L[(size_t)2048 * D_MODEL];
__device__ __half g_W2H[(size_t)512 * H_DIM];        // [n=512,k=1024], x32
__device__ __half g_W2L[(size_t)512 * H_DIM];
__device__ __half g_h16[(size_t)SB * H_DIM];         // h, single fp16 (128 MB)
__device__ int g_is64, g_mask32;

// ---------------- PTX helpers (sm_80+ portable) ----------------
__device__ __forceinline__ uint32_t smem_u32(const void* p) {
    uint32_t a;
    asm("{ .reg .u64 t; cvta.to.shared.u64 t, %1; cvt.u32.u64 %0, t; }"
        : "=r"(a) : "l"(p));
    return a;
}
__device__ __forceinline__ void cp16(uint32_t dst, const void* src) {
    asm volatile("cp.async.cg.shared.global [%0], [%1], 16;"
                 :: "r"(dst), "l"(src));
}
#define CP_COMMIT() asm volatile("cp.async.commit_group;" ::: "memory")
#define CP_WAIT(n)  asm volatile("cp.async.wait_group %0;" :: "n"(n) : "memory")

__device__ __forceinline__ void ldsm_x4(uint32_t* r, uint32_t addr) {
    asm volatile("ldmatrix.sync.aligned.m8n8.x4.shared.b16 {%0,%1,%2,%3}, [%4];"
                 : "=r"(r[0]), "=r"(r[1]), "=r"(r[2]), "=r"(r[3]) : "r"(addr));
}
__device__ __forceinline__ void mma16816(float* c, const uint32_t* a,
                                         uint32_t b0, uint32_t b1) {
    asm volatile(
        "mma.sync.aligned.m16n8k16.row.col.f32.f16.f16.f32 "
        "{%0,%1,%2,%3}, {%4,%5,%6,%7}, {%8,%9}, {%0,%1,%2,%3};"
        : "+f"(c[0]), "+f"(c[1]), "+f"(c[2]), "+f"(c[3])
        : "r"(a[0]), "r"(a[1]), "r"(a[2]), "r"(a[3]), "r"(b0), "r"(b1));
}

// ---------------- dtype detection ----------------
__global__ void detect_kernel(const unsigned int* __restrict__ cw,
                              const unsigned char* __restrict__ mk) {
    unsigned int v = cw[2 * threadIdx.x + 1];
    unsigned int any_c = __ballot_sync(0xffffffffu, v != 0u);
    unsigned char mb = (unsigned char)(mk[4 * threadIdx.x + 1] |
                                       mk[4 * threadIdx.x + 2] |
                                       mk[4 * threadIdx.x + 3]);
    unsigned int any_m = __ballot_sync(0xffffffffu, mb != 0);
    if (threadIdx.x == 0) {
        g_is64   = (any_c == 0u) ? 1 : 0;
        g_mask32 = (any_m == 0u) ? 1 : 0;
    }
}

// ---------------- tiny GEMM: TQ and DW (fp32 exact) ----------------
__global__ void emb_kernel(const float* __restrict__ type_emb,
                           const float* __restrict__ dir_emb,
                           const float* __restrict__ W1) {
    __shared__ float se[D_MODEL];
    int bid = blockIdx.x;
    const float* e = (bid < 8) ? (type_emb + bid * D_MODEL)
                               : (dir_emb + (bid - 8) * D_MODEL);
    const float* W = (bid < 8) ? W1 : (W1 + (size_t)1536 * H_DIM);
    float* out = (bid < 8) ? (g_TQ + bid * H_DIM) : (g_DW + (bid - 8) * H_DIM);
    int tid = threadIdx.x;
    se[tid] = e[tid]; se[tid + 256] = e[tid + 256];
    __syncthreads();
    float a0 = 0.f, a1 = 0.f, a2 = 0.f, a3 = 0.f;
    for (int i = 0; i < D_MODEL; i++) {
        float ev = se[i];
        const float* wr = W + (size_t)i * H_DIM + tid;
        a0 = fmaf(ev, wr[0], a0); a1 = fmaf(ev, wr[256], a1);
        a2 = fmaf(ev, wr[512], a2); a3 = fmaf(ev, wr[768], a3);
    }
    out[tid] = a0; out[tid+256] = a1; out[tid+512] = a2; out[tid+768] = a3;
}

// ---------------- fp32 -> fp16 hi/lo splits ----------------
__device__ __forceinline__ void split16(float v, __half& h, __half& l) {
    h = __float2half_rn(v);
    l = __float2half_rn(v - __half2float(h));
}

__global__ void split_obj_kernel(const float* __restrict__ src) {
    size_t i = (size_t)blockIdx.x * 256 + threadIdx.x;
    __half h, l;
    split16(src[i], h, l);
    g_objH[i] = h; g_objL[i] = l;
}

__global__ void w1t_kernel(const float* __restrict__ W1) {
    int idx = blockIdx.x * 256 + threadIdx.x;   // 2048*512
    int n = idx >> 9;
    int k = idx & 511;
    int col = n & 1023;
    int row = ((n < 1024) ? 512 : 1024) + k;
    float v = W1[(size_t)row * H_DIM + col] * W1_SCALE;
    __half h, l; split16(v, h, l);
    g_W1H[idx] = h; g_W1L[idx] = l;
}

__global__ void w2t_kernel(const float* __restrict__ W2) {
    int idx = blockIdx.x * 256 + threadIdx.x;   // 512*1024
    int n = idx >> 10;
    int k = idx & 1023;
    float v = W2[(size_t)k * 512 + n] * W2_SCALE;
    __half h, l; split16(v, h, l);
    g_W2H[idx] = h; g_W2L[idx] = l;
}

// ---------------- build h (single fp16) ----------------
__global__ __launch_bounds__(256) void build_h_kernel(
    const unsigned int* __restrict__ cons,
    const unsigned char* __restrict__ mask,
    const float* __restrict__ b1)
{
    const int row = blockIdx.x;
    const int b = row & 127;
    const int s = row >> 7;

    int t, q, r, dd;
    size_t base = (size_t)row * 4;
    if (g_is64) {
        t  = (int)cons[(base + 0) * 2]; q  = (int)cons[(base + 1) * 2];
        r  = (int)cons[(base + 2) * 2]; dd = (int)cons[(base + 3) * 2];
    } else {
        t = (int)cons[base]; q = (int)cons[base + 1];
        r = (int)cons[base + 2]; dd = (int)cons[base + 3];
    }
    bool pad = g_mask32 ? (((const int*)mask)[(size_t)b * S_DIM + s] != 0)
                        : (mask[(size_t)b * S_DIM + s] != 0);
    const bool se = (t == 4) || (t == 5);
    const bool orient = (t == 2) || (t == 3);
    const float ft = pad ? 0.f : 1.f;
    const float fq = (pad || se) ? (0.f) : (1.0f / W1_SCALE);  // undo QR scale
    const float fd = (pad || se || orient) ? 0.f : 1.f;

    int i = threadIdx.x;
    const float4 A  = ((const float4*)(g_TQ + (size_t)t * H_DIM))[i];
    const float4 Q  = ((const float4*)(g_QR + (size_t)(q * B_DIM + b) * 2048))[i];
    const float4 R  = ((const float4*)(g_QR + (size_t)(r * B_DIM + b) * 2048 + 1024))[i];
    const float4 D  = ((const float4*)(g_DW + (size_t)dd * H_DIM))[i];
    const float4 Bv = ((const float4*)b1)[i];

    float o0 = fmaxf(ft * A.x + fq * (Q.x + R.x) + fd * D.x + Bv.x, 0.f);
    float o1 = fmaxf(ft * A.y + fq * (Q.y + R.y) + fd * D.y + Bv.y, 0.f);
    float o2 = fmaxf(ft * A.z + fq * (Q.z + R.z) + fd * D.z + Bv.z, 0.f);
    float o3 = fmaxf(ft * A.w + fq * (Q.w + R.w) + fd * D.w + Bv.w, 0.f);

    __half2* ph = (__half2*)(g_h16 + (size_t)row * H_DIM);
    ph[2*i]   = __half2(__float2half_rn(o0), __float2half_rn(o1));
    ph[2*i+1] = __half2(__float2half_rn(o2), __float2half_rn(o3));
}

// ======================================================================
// GEMM 1 (QR): C[8192,2048] = (Ah+Al)[8192,512] @ (Bh+Bl)[2048,512]^T
// 3-term fp16 split. CTA 128x128, 4 warps of 64x64, BK=32, 3-stage.
// SMEM rows: 32 fp16 = 64B = 4x16B units; swizzle u' = u ^ ((row>>1)&3).
// ======================================================================
#define QR_STAGE 32768   // Ah 8K | Al 8K | Bh 8K | Bl 8K
#define QR_NST   3

__device__ __forceinline__ void qr_load_chunk(
    uint32_t sm, const __half* Ah, const __half* Al,
    const __half* Bh, const __half* Bl,
    int m0, int n0, int k0, int K, int tid)
{
#pragma unroll
    for (int i = 0; i < 4; i++) {
        int u_lin = tid + i * 128;          // 0..511
        int m = u_lin >> 2, u = u_lin & 3;
        int up = u ^ ((m >> 1) & 3);
        uint32_t d = sm + m * 64 + up * 16;
        size_t ga = (size_t)(m0 + m) * K + k0 + u * 8;
        size_t gb = (size_t)(n0 + m) * K + k0 + u * 8;
        cp16(d,          Ah + ga);
        cp16(d + 8192,   Al + ga);
        cp16(d + 16384,  Bh + gb);
        cp16(d + 24576,  Bl + gb);
    }
}

__global__ __launch_bounds__(128, 2) void qr_gemm_kernel(
    const __half* __restrict__ Ah, const __half* __restrict__ Al,
    const __half* __restrict__ Bh, const __half* __restrict__ Bl,
    float* __restrict__ C, int K, int ldc)
{
    extern __shared__ char smem[];
    const uint32_t sb = smem_u32(smem);
    const int tid = threadIdx.x;
    const int wid = tid >> 5, lid = tid & 31;
    const int m0 = blockIdx.y * 128;
    const int n0 = blockIdx.x * 128;
    const int wm0 = (wid & 1) * 64;
    const int wn0 = (wid >> 1) * 64;

    float acc[4][8][4];
#pragma unroll
    for (int i = 0; i < 4; i++)
#pragma unroll
        for (int j = 0; j < 8; j++)
#pragma unroll
            for (int k = 0; k < 4; k++) acc[i][j][k] = 0.f;

    const int a_r = (lid & 15);
    const int a_u = (lid >> 4);
    const int b_r = (lid & 7) + ((lid >> 4) << 3);
    const int b_u = ((lid >> 3) & 1);

    const int nch = K >> 5;
    qr_load_chunk(sb, Ah, Al, Bh, Bl, m0, n0, 0, K, tid);
    CP_COMMIT();
    qr_load_chunk(sb + QR_STAGE, Ah, Al, Bh, Bl, m0, n0, 32, K, tid);
    CP_COMMIT();

    for (int ch = 0; ch < nch; ch++) {
        if (ch + 1 < nch) { CP_WAIT(1); } else { CP_WAIT(0); }
        __syncthreads();
        const uint32_t stage = sb + (ch % QR_NST) * QR_STAGE;

#pragma unroll
        for (int ks = 0; ks < 2; ks++) {
            uint32_t bh[4][4], bl[4][4];
#pragma unroll
            for (int bi = 0; bi < 4; bi++) {
                int n = wn0 + bi * 16 + b_r;
                int u = ks * 2 + b_u;
                int up = u ^ ((n >> 1) & 3);
                ldsm_x4(bh[bi], stage + 16384u + n * 64 + up * 16);
                ldsm_x4(bl[bi], stage + 24576u + n * 64 + up * 16);
            }
#pragma unroll
            for (int mt = 0; mt < 4; mt++) {
                uint32_t ah[4], al[4];
                int m = wm0 + mt * 16 + a_r;
                int u = ks * 2 + a_u;
                int up = u ^ ((m >> 1) & 3);
                ldsm_x4(ah, stage + m * 64 + up * 16);
                ldsm_x4(al, stage + 8192u + m * 64 + up * 16);
#pragma unroll
                for (int nt = 0; nt < 8; nt++) {
                    uint32_t b0 = bh[nt >> 1][(nt & 1) * 2];
                    uint32_t b1 = bh[nt >> 1][(nt & 1) * 2 + 1];
                    uint32_t c0 = bl[nt >> 1][(nt & 1) * 2];
                    uint32_t c1 = bl[nt >> 1][(nt & 1) * 2 + 1];
                    mma16816(acc[mt][nt], ah, b0, b1);   // Ah*Bh
                    mma16816(acc[mt][nt], ah, c0, c1);   // Ah*Bl
                    mma16816(acc[mt][nt], al, b0, b1);   // Al*Bh
                }
            }
        }
        if (ch + 2 < nch) {
            qr_load_chunk(sb + ((ch + 2) % QR_NST) * QR_STAGE,
                          Ah, Al, Bh, Bl, m0, n0, (ch + 2) * 32, K, tid);
            CP_COMMIT();
        }
    }

    const int gr = lid >> 2;
    const int gc = (lid & 3) * 2;
#pragma unroll
    for (int nt = 0; nt < 8; nt++) {
        int col = n0 + wn0 + nt * 8 + gc;
#pragma unroll
        for (int mt = 0; mt < 4; mt++) {
            int row = m0 + wm0 + mt * 16 + gr;
            *(float2*)&C[(size_t)row * ldc + col] =
                make_float2(acc[mt][nt][0], acc[mt][nt][1]);
            *(float2*)&C[(size_t)(row + 8) * ldc + col] =
                make_float2(acc[mt][nt][2], acc[mt][nt][3]);
        }
    }
}

// ======================================================================
// GEMM 2 (out): C[65536,512] = A[65536,1024] @ (Bh+Bl)[512,1024]^T
// 2-term: A single fp16, B split. CTA 128x256, 8 warps of 64x64, BK=32,
// 3-stage. Epilogue: acc*(1/W2_SCALE) + bias.
// SMEM/stage: A 8K @0 | Bh 16K @8192 | Bl 16K @24576  = 40960 B
// ======================================================================
#define OG_STAGE 40960
#define OG_NST   3

__device__ __forceinline__ void og_load_chunk(
    uint32_t sm, const __half* A, const __half* Bh, const __half* Bl,
    int m0, int n0, int k0, int K, int tid)
{
#pragma unroll
    for (int i = 0; i < 2; i++) {           // A: 512 units
        int u_lin = tid + i * 256;
        int m = u_lin >> 2, u = u_lin & 3;
        int up = u ^ ((m >> 1) & 3);
        cp16(sm + m * 64 + up * 16, A + (size_t)(m0 + m) * K + k0 + u * 8);
    }
#pragma unroll
    for (int i = 0; i < 4; i++) {           // B: 1024 units x2 arrays
        int u_lin = tid + i * 256;
        int n = u_lin >> 2, u = u_lin & 3;
        int up = u ^ ((n >> 1) & 3);
        uint32_t d = sm + 8192 + n * 64 + up * 16;
        size_t gb = (size_t)(n0 + n) * K + k0 + u * 8;
        cp16(d,          Bh + gb);
        cp16(d + 16384,  Bl + gb);
    }
}

__global__ __launch_bounds__(256, 1) void out_gemm_kernel(
    const __half* __restrict__ A,
    const __half* __restrict__ Bh, const __half* __restrict__ Bl,
    const float* __restrict__ bias, float* __restrict__ C,
    int K, int ldc)
{
    extern __shared__ char smem[];
    const uint32_t sb = smem_u32(smem);
    const int tid = threadIdx.x;
    const int wid = tid >> 5, lid = tid & 31;
    const int m0 = blockIdx.y * 128;
    const int n0 = blockIdx.x * 256;
    const int wm0 = (wid & 1) * 64;
    const int wn0 = (wid >> 1) * 64;        // 4 N-warps cover 256

    float acc[4][8][4];
#pragma unroll
    for (int i = 0; i < 4; i++)
#pragma unroll
        for (int j = 0; j < 8; j++)
#pragma unroll
            for (int k = 0; k < 4; k++) acc[i][j][k] = 0.f;

    const int a_r = (lid & 15);
    const int a_u = (lid >> 4);
    const int b_r = (lid & 7) + ((lid >> 4) << 3);
    const int b_u = ((lid >> 3) & 1);

    const int nch = K >> 5;
    og_load_chunk(sb, A, Bh, Bl, m0, n0, 0, K, tid);
    CP_COMMIT();
    og_load_chunk(sb + OG_STAGE, A, Bh, Bl, m0, n0, 32, K, tid);
    CP_COMMIT();

    for (int ch = 0; ch < nch; ch++) {
        if (ch + 1 < nch) { CP_WAIT(1); } else { CP_WAIT(0); }
        __syncthreads();
        const uint32_t stage = sb + (ch % OG_NST) * OG_STAGE;

#pragma unroll
        for (int ks = 0; ks < 2; ks++) {
            uint32_t bh[4][4], bl[4][4];
#pragma unroll
            for (int bi = 0; bi < 4; bi++) {
                int n = wn0 + bi * 16 + b_r;
                int u = ks * 2 + b_u;
                int up = u ^ ((n >> 1) & 3);
                ldsm_x4(bh[bi], stage + 8192u  + n * 64 + up * 16);
                ldsm_x4(bl[bi], stage + 24576u + n * 64 + up * 16);
            }
#pragma unroll
            for (int mt = 0; mt < 4; mt++) {
                uint32_t af[4];
                int m = wm0 + mt * 16 + a_r;
                int u = ks * 2 + a_u;
                int up = u ^ ((m >> 1) & 3);
                ldsm_x4(af, stage + m * 64 + up * 16);
#pragma unroll
                for (int nt = 0; nt < 8; nt++) {
                    mma16816(acc[mt][nt], af,
                             bh[nt >> 1][(nt & 1) * 2], bh[nt >> 1][(nt & 1) * 2 + 1]);
                    mma16816(acc[mt][nt], af,
                             bl[nt >> 1][(nt & 1) * 2], bl[nt >> 1][(nt & 1) * 2 + 1]);
                }
            }
        }
        if (ch + 2 < nch) {
            og_load_chunk(sb + ((ch + 2) % OG_NST) * OG_STAGE,
                          A, Bh, Bl, m0, n0, (ch + 2) * 32, K, tid);
            CP_COMMIT();
        }
    }

    const float inv = 1.0f / W2_SCALE;
    const int gr = lid >> 2;
    const int gc = (lid & 3) * 2;
#pragma unroll
    for (int nt = 0; nt < 8; nt++) {
        int col = n0 + wn0 + nt * 8 + gc;
        float bx = bias[col], by = bias[col + 1];
#pragma unroll
        for (int mt = 0; mt < 4; mt++) {
            int row = m0 + wm0 + mt * 16 + gr;
            *(float2*)&C[(size_t)row * ldc + col] =
                make_float2(fmaf(acc[mt][nt][0], inv, bx),
                            fmaf(acc[mt][nt][1], inv, by));
            *(float2*)&C[(size_t)(row + 8) * ldc + col] =
                make_float2(fmaf(acc[mt][nt][2], inv, bx),
                            fmaf(acc[mt][nt][3], inv, by));
        }
    }
}

// ---------------- launch ----------------
extern "C" void kernel_launch(void* const* d_in, const int* in_sizes, int n_in,
                              void* d_out, int out_size) {
    const unsigned int*  constraints = (const unsigned int*)d_in[0];
    const unsigned char* mask        = (const unsigned char*)d_in[1];
    const float* obj_e    = (const float*)d_in[2];
    const float* type_emb = (const float*)d_in[3];
    const float* dir_emb  = (const float*)d_in[4];
    const float* W1       = (const float*)d_in[5];
    const float* b1       = (const float*)d_in[6];
    const float* W2       = (const float*)d_in[7];
    const float* b2       = (const float*)d_in[8];
    float* out = (float*)d_out;

    float* pQR;
    __half *pOH, *pOL, *pW1H, *pW1L, *pW2H, *pW2L, *pH16;
    cudaGetSymbolAddress((void**)&pQR,  g_QR);
    cudaGetSymbolAddress((void**)&pOH,  g_objH);
    cudaGetSymbolAddress((void**)&pOL,  g_objL);
    cudaGetSymbolAddress((void**)&pW1H, g_W1H);
    cudaGetSymbolAddress((void**)&pW1L, g_W1L);
    cudaGetSymbolAddress((void**)&pW2H, g_W2H);
    cudaGetSymbolAddress((void**)&pW2L, g_W2L);
    cudaGetSymbolAddress((void**)&pH16, g_h16);

    cudaFuncSetAttribute(qr_gemm_kernel,
                         cudaFuncAttributeMaxDynamicSharedMemorySize,
                         QR_NST * QR_STAGE);
    cudaFuncSetAttribute(out_gemm_kernel,
                         cudaFuncAttributeMaxDynamicSharedMemorySize,
                         OG_NST * OG_STAGE);

    // 0) dtype detection
    detect_kernel<<<1, 32>>>(constraints, mask);
    // 1) TQ / DW (fp32 exact, tiny)
    emb_kernel<<<16, 256>>>(type_emb, dir_emb, W1);
    // 2) fp16 splits (weights pre-scaled)
    split_obj_kernel<<<(NB * D_MODEL) / 256, 256>>>(obj_e);
    w1t_kernel<<<(2048 * 512) / 256, 256>>>(W1);
    w2t_kernel<<<(512 * 1024) / 256, 256>>>(W2);
    // 3) QR = obj_e @ [W1_q | W1_r] * 64  (fp16 3-term HMMA)
    {
        dim3 grid(2048 / 128, NB / 128);   // (16, 64)
        qr_gemm_kernel<<<grid, 128, QR_NST * QR_STAGE>>>(
            pOH, pOL, pW1H, pW1L, pQR, D_MODEL, 2048);
    }
    // 4) h = relu(gather-sum + b1) -> single fp16
    build_h_kernel<<<SB, 256>>>(constraints, mask, b1);
    // 5) out = h @ W2 + b2  (fp16 2-term HMMA, tile 128x256)
    {
        dim3 grid(512 / 256, SB / 128);    // (2, 512)
        out_gemm_kernel<<<grid, 256, OG_NST * OG_STAGE>>>(
            pH16, pW2H, pW2L, b2, out, H_DIM, 512);
    }
}

// round 7
// speedup vs baseline: 4.4177x; 1.3444x over previous
#include <cuda_runtime.h>
#include <cuda_bf16.h>
#include <cuda_fp16.h>
#include <cstdint>

// ---------------- problem constants ----------------
#define S_DIM   512
#define B_DIM   128
#define N_OBJ   64
#define D_MODEL 512
#define H_DIM   1024
#define SB      (S_DIM * B_DIM)     // 65536
#define NB      (N_OBJ * B_DIM)     // 8192

// W1 pre-scale keeps its fp16 lo-part out of subnormal range
#define W1_SCALE 64.0f

// ---------------- device scratch ----------------
__device__ float g_TQ[8 * H_DIM];
__device__ float g_DW[8 * H_DIM];
__device__ float g_QR[(size_t)NB * 2048];            // scaled by W1_SCALE
__device__ __half g_objH[(size_t)NB * D_MODEL];      // obj_e, single fp16
__device__ __half g_W1H[(size_t)2048 * D_MODEL];     // [n=2048,k=512], x64
__device__ __half g_W1L[(size_t)2048 * D_MODEL];
__device__ __half g_W2H[(size_t)512 * H_DIM];        // [n=512,k=1024], single
__device__ __half g_h16[(size_t)SB * H_DIM];         // h, single fp16 (128 MB)
__device__ int g_is64, g_mask32;

// ---------------- PTX helpers (sm_80+ portable) ----------------
__device__ __forceinline__ uint32_t smem_u32(const void* p) {
    uint32_t a;
    asm("{ .reg .u64 t; cvta.to.shared.u64 t, %1; cvt.u32.u64 %0, t; }"
        : "=r"(a) : "l"(p));
    return a;
}
__device__ __forceinline__ void cp16(uint32_t dst, const void* src) {
    asm volatile("cp.async.cg.shared.global [%0], [%1], 16;"
                 :: "r"(dst), "l"(src));
}
#define CP_COMMIT() asm volatile("cp.async.commit_group;" ::: "memory")
#define CP_WAIT(n)  asm volatile("cp.async.wait_group %0;" :: "n"(n) : "memory")

__device__ __forceinline__ void ldsm_x4(uint32_t* r, uint32_t addr) {
    asm volatile("ldmatrix.sync.aligned.m8n8.x4.shared.b16 {%0,%1,%2,%3}, [%4];"
                 : "=r"(r[0]), "=r"(r[1]), "=r"(r[2]), "=r"(r[3]) : "r"(addr));
}
__device__ __forceinline__ void mma16816(float* c, const uint32_t* a,
                                         uint32_t b0, uint32_t b1) {
    asm volatile(
        "mma.sync.aligned.m16n8k16.row.col.f32.f16.f16.f32 "
        "{%0,%1,%2,%3}, {%4,%5,%6,%7}, {%8,%9}, {%0,%1,%2,%3};"
        : "+f"(c[0]), "+f"(c[1]), "+f"(c[2]), "+f"(c[3])
        : "r"(a[0]), "r"(a[1]), "r"(a[2]), "r"(a[3]), "r"(b0), "r"(b1));
}

// ---------------- dtype detection ----------------
__global__ void detect_kernel(const unsigned int* __restrict__ cw,
                              const unsigned char* __restrict__ mk) {
    unsigned int v = cw[2 * threadIdx.x + 1];
    unsigned int any_c = __ballot_sync(0xffffffffu, v != 0u);
    unsigned char mb = (unsigned char)(mk[4 * threadIdx.x + 1] |
                                       mk[4 * threadIdx.x + 2] |
                                       mk[4 * threadIdx.x + 3]);
    unsigned int any_m = __ballot_sync(0xffffffffu, mb != 0);
    if (threadIdx.x == 0) {
        g_is64   = (any_c == 0u) ? 1 : 0;
        g_mask32 = (any_m == 0u) ? 1 : 0;
    }
}

// ---------------- tiny GEMM: TQ and DW (fp32 exact) ----------------
__global__ void emb_kernel(const float* __restrict__ type_emb,
                           const float* __restrict__ dir_emb,
                           const float* __restrict__ W1) {
    __shared__ float se[D_MODEL];
    int bid = blockIdx.x;
    const float* e = (bid < 8) ? (type_emb + bid * D_MODEL)
                               : (dir_emb + (bid - 8) * D_MODEL);
    const float* W = (bid < 8) ? W1 : (W1 + (size_t)1536 * H_DIM);
    float* out = (bid < 8) ? (g_TQ + bid * H_DIM) : (g_DW + (bid - 8) * H_DIM);
    int tid = threadIdx.x;
    se[tid] = e[tid]; se[tid + 256] = e[tid + 256];
    __syncthreads();
    float a0 = 0.f, a1 = 0.f, a2 = 0.f, a3 = 0.f;
    for (int i = 0; i < D_MODEL; i++) {
        float ev = se[i];
        const float* wr = W + (size_t)i * H_DIM + tid;
        a0 = fmaf(ev, wr[0], a0); a1 = fmaf(ev, wr[256], a1);
        a2 = fmaf(ev, wr[512], a2); a3 = fmaf(ev, wr[768], a3);
    }
    out[tid] = a0; out[tid+256] = a1; out[tid+512] = a2; out[tid+768] = a3;
}

// ---------------- conversions ----------------
__device__ __forceinline__ void split16(float v, __half& h, __half& l) {
    h = __float2half_rn(v);
    l = __float2half_rn(v - __half2float(h));
}

__global__ void conv_obj_kernel(const float* __restrict__ src) {
    size_t i = (size_t)blockIdx.x * 256 + threadIdx.x;
    g_objH[i] = __float2half_rn(src[i]);
}

__global__ void w1t_kernel(const float* __restrict__ W1) {
    int idx = blockIdx.x * 256 + threadIdx.x;   // 2048*512
    int n = idx >> 9;
    int k = idx & 511;
    int col = n & 1023;
    int row = ((n < 1024) ? 512 : 1024) + k;
    float v = W1[(size_t)row * H_DIM + col] * W1_SCALE;
    __half h, l; split16(v, h, l);
    g_W1H[idx] = h; g_W1L[idx] = l;
}

__global__ void w2t_kernel(const float* __restrict__ W2) {
    int idx = blockIdx.x * 256 + threadIdx.x;   // 512*1024
    int n = idx >> 10;
    int k = idx & 1023;
    g_W2H[idx] = __float2half_rn(W2[(size_t)k * 512 + n]);
}

// ---------------- build h (single fp16) ----------------
__global__ __launch_bounds__(256) void build_h_kernel(
    const unsigned int* __restrict__ cons,
    const unsigned char* __restrict__ mask,
    const float* __restrict__ b1)
{
    const int row = blockIdx.x;
    const int b = row & 127;
    const int s = row >> 7;

    int t, q, r, dd;
    size_t base = (size_t)row * 4;
    if (g_is64) {
        t  = (int)cons[(base + 0) * 2]; q  = (int)cons[(base + 1) * 2];
        r  = (int)cons[(base + 2) * 2]; dd = (int)cons[(base + 3) * 2];
    } else {
        t = (int)cons[base]; q = (int)cons[base + 1];
        r = (int)cons[base + 2]; dd = (int)cons[base + 3];
    }
    bool pad = g_mask32 ? (((const int*)mask)[(size_t)b * S_DIM + s] != 0)
                        : (mask[(size_t)b * S_DIM + s] != 0);
    const bool se = (t == 4) || (t == 5);
    const bool orient = (t == 2) || (t == 3);
    const float ft = pad ? 0.f : 1.f;
    const float fq = (pad || se) ? (0.f) : (1.0f / W1_SCALE);  // undo QR scale
    const float fd = (pad || se || orient) ? 0.f : 1.f;

    int i = threadIdx.x;
    const float4 A  = ((const float4*)(g_TQ + (size_t)t * H_DIM))[i];
    const float4 Q  = ((const float4*)(g_QR + (size_t)(q * B_DIM + b) * 2048))[i];
    const float4 R  = ((const float4*)(g_QR + (size_t)(r * B_DIM + b) * 2048 + 1024))[i];
    const float4 D  = ((const float4*)(g_DW + (size_t)dd * H_DIM))[i];
    const float4 Bv = ((const float4*)b1)[i];

    float o0 = fmaxf(ft * A.x + fq * (Q.x + R.x) + fd * D.x + Bv.x, 0.f);
    float o1 = fmaxf(ft * A.y + fq * (Q.y + R.y) + fd * D.y + Bv.y, 0.f);
    float o2 = fmaxf(ft * A.z + fq * (Q.z + R.z) + fd * D.z + Bv.z, 0.f);
    float o3 = fmaxf(ft * A.w + fq * (Q.w + R.w) + fd * D.w + Bv.w, 0.f);

    __half2* ph = (__half2*)(g_h16 + (size_t)row * H_DIM);
    ph[2*i]   = __half2(__float2half_rn(o0), __float2half_rn(o1));
    ph[2*i+1] = __half2(__float2half_rn(o2), __float2half_rn(o3));
}

// ======================================================================
// GEMM 1 (QR): C[8192,2048] = A[8192,512] @ (Bh+Bl)[2048,512]^T
// 2-term: A single fp16, B split. CTA 128x128, 4 warps of 64x64, BK=32,
// 3-stage. SMEM/stage: A 8K @0 | Bh 8K @8192 | Bl 8K @16384 = 24576 B.
// Swizzle u' = u ^ ((row>>1)&3) on 16B units of 64B rows.
// ======================================================================
#define QR_STAGE 24576
#define QR_NST   3

__device__ __forceinline__ void qr_load_chunk(
    uint32_t sm, const __half* A, const __half* Bh, const __half* Bl,
    int m0, int n0, int k0, int K, int tid)
{
#pragma unroll
    for (int i = 0; i < 4; i++) {
        int u_lin = tid + i * 128;          // 0..511
        int m = u_lin >> 2, u = u_lin & 3;
        int up = u ^ ((m >> 1) & 3);
        uint32_t d = sm + m * 64 + up * 16;
        size_t ga = (size_t)(m0 + m) * K + k0 + u * 8;
        size_t gb = (size_t)(n0 + m) * K + k0 + u * 8;
        cp16(d,          A + ga);
        cp16(d + 8192,   Bh + gb);
        cp16(d + 16384,  Bl + gb);
    }
}

__global__ __launch_bounds__(128, 2) void qr_gemm_kernel(
    const __half* __restrict__ A,
    const __half* __restrict__ Bh, const __half* __restrict__ Bl,
    float* __restrict__ C, int K, int ldc)
{
    extern __shared__ char smem[];
    const uint32_t sb = smem_u32(smem);
    const int tid = threadIdx.x;
    const int wid = tid >> 5, lid = tid & 31;
    const int m0 = blockIdx.y * 128;
    const int n0 = blockIdx.x * 128;
    const int wm0 = (wid & 1) * 64;
    const int wn0 = (wid >> 1) * 64;

    float acc[4][8][4];
#pragma unroll
    for (int i = 0; i < 4; i++)
#pragma unroll
        for (int j = 0; j < 8; j++)
#pragma unroll
            for (int k = 0; k < 4; k++) acc[i][j][k] = 0.f;

    const int a_r = (lid & 15);
    const int a_u = (lid >> 4);
    const int b_r = (lid & 7) + ((lid >> 4) << 3);
    const int b_u = ((lid >> 3) & 1);

    const int nch = K >> 5;
    qr_load_chunk(sb, A, Bh, Bl, m0, n0, 0, K, tid);
    CP_COMMIT();
    qr_load_chunk(sb + QR_STAGE, A, Bh, Bl, m0, n0, 32, K, tid);
    CP_COMMIT();

    for (int ch = 0; ch < nch; ch++) {
        if (ch + 1 < nch) { CP_WAIT(1); } else { CP_WAIT(0); }
        __syncthreads();
        const uint32_t stage = sb + (ch % QR_NST) * QR_STAGE;

#pragma unroll
        for (int ks = 0; ks < 2; ks++) {
            uint32_t bh[4][4], bl[4][4];
#pragma unroll
            for (int bi = 0; bi < 4; bi++) {
                int n = wn0 + bi * 16 + b_r;
                int u = ks * 2 + b_u;
                int up = u ^ ((n >> 1) & 3);
                ldsm_x4(bh[bi], stage + 8192u  + n * 64 + up * 16);
                ldsm_x4(bl[bi], stage + 16384u + n * 64 + up * 16);
            }
#pragma unroll
            for (int mt = 0; mt < 4; mt++) {
                uint32_t af[4];
                int m = wm0 + mt * 16 + a_r;
                int u = ks * 2 + a_u;
                int up = u ^ ((m >> 1) & 3);
                ldsm_x4(af, stage + m * 64 + up * 16);
#pragma unroll
                for (int nt = 0; nt < 8; nt++) {
                    mma16816(acc[mt][nt], af,
                             bh[nt >> 1][(nt & 1) * 2], bh[nt >> 1][(nt & 1) * 2 + 1]);
                    mma16816(acc[mt][nt], af,
                             bl[nt >> 1][(nt & 1) * 2], bl[nt >> 1][(nt & 1) * 2 + 1]);
                }
            }
        }
        if (ch + 2 < nch) {
            qr_load_chunk(sb + ((ch + 2) % QR_NST) * QR_STAGE,
                          A, Bh, Bl, m0, n0, (ch + 2) * 32, K, tid);
            CP_COMMIT();
        }
    }

    const int gr = lid >> 2;
    const int gc = (lid & 3) * 2;
#pragma unroll
    for (int nt = 0; nt < 8; nt++) {
        int col = n0 + wn0 + nt * 8 + gc;
#pragma unroll
        for (int mt = 0; mt < 4; mt++) {
            int row = m0 + wm0 + mt * 16 + gr;
            *(float2*)&C[(size_t)row * ldc + col] =
                make_float2(acc[mt][nt][0], acc[mt][nt][1]);
            *(float2*)&C[(size_t)(row + 8) * ldc + col] =
                make_float2(acc[mt][nt][2], acc[mt][nt][3]);
        }
    }
}

// ======================================================================
// GEMM 2 (out): C[65536,512] = A[65536,1024] @ B[512,1024]^T + bias
// 1-term: A and B single fp16. CTA 128x256, 8 warps of 64x64, BK=32,
// 4-stage pipeline. SMEM/stage: A 8K @0 | B 16K @8192 = 24576 B.
// ======================================================================
#define OG_STAGE 24576
#define OG_NST   4

__device__ __forceinline__ void og_load_chunk(
    uint32_t sm, const __half* A, const __half* B,
    int m0, int n0, int k0, int K, int tid)
{
#pragma unroll
    for (int i = 0; i < 2; i++) {           // A: 512 units
        int u_lin = tid + i * 256;
        int m = u_lin >> 2, u = u_lin & 3;
        int up = u ^ ((m >> 1) & 3);
        cp16(sm + m * 64 + up * 16, A + (size_t)(m0 + m) * K + k0 + u * 8);
    }
#pragma unroll
    for (int i = 0; i < 4; i++) {           // B: 1024 units
        int u_lin = tid + i * 256;
        int n = u_lin >> 2, u = u_lin & 3;
        int up = u ^ ((n >> 1) & 3);
        cp16(sm + 8192 + n * 64 + up * 16, B + (size_t)(n0 + n) * K + k0 + u * 8);
    }
}

__global__ __launch_bounds__(256, 1) void out_gemm_kernel(
    const __half* __restrict__ A, const __half* __restrict__ B,
    const float* __restrict__ bias, float* __restrict__ C,
    int K, int ldc)
{
    extern __shared__ char smem[];
    const uint32_t sb = smem_u32(smem);
    const int tid = threadIdx.x;
    const int wid = tid >> 5, lid = tid & 31;
    const int m0 = blockIdx.y * 128;
    const int n0 = blockIdx.x * 256;
    const int wm0 = (wid & 1) * 64;
    const int wn0 = (wid >> 1) * 64;

    float acc[4][8][4];
#pragma unroll
    for (int i = 0; i < 4; i++)
#pragma unroll
        for (int j = 0; j < 8; j++)
#pragma unroll
            for (int k = 0; k < 4; k++) acc[i][j][k] = 0.f;

    const int a_r = (lid & 15);
    const int a_u = (lid >> 4);
    const int b_r = (lid & 7) + ((lid >> 4) << 3);
    const int b_u = ((lid >> 3) & 1);

    const int nch = K >> 5;     // 32
    og_load_chunk(sb,                A, B, m0, n0, 0,  K, tid);  CP_COMMIT();
    og_load_chunk(sb + OG_STAGE,     A, B, m0, n0, 32, K, tid);  CP_COMMIT();
    og_load_chunk(sb + 2 * OG_STAGE, A, B, m0, n0, 64, K, tid);  CP_COMMIT();

    for (int ch = 0; ch < nch; ch++) {
        if (ch + 3 <= nch) { CP_WAIT(2); }
        else if (ch + 2 == nch) { CP_WAIT(1); }
        else { CP_WAIT(0); }
        __syncthreads();
        const uint32_t stage = sb + (ch % OG_NST) * OG_STAGE;

#pragma unroll
        for (int ks = 0; ks < 2; ks++) {
            uint32_t bf[4][4];
#pragma unroll
            for (int bi = 0; bi < 4; bi++) {
                int n = wn0 + bi * 16 + b_r;
                int u = ks * 2 + b_u;
                int up = u ^ ((n >> 1) & 3);
                ldsm_x4(bf[bi], stage + 8192u + n * 64 + up * 16);
            }
#pragma unroll
            for (int mt = 0; mt < 4; mt++) {
                uint32_t af[4];
                int m = wm0 + mt * 16 + a_r;
                int u = ks * 2 + a_u;
                int up = u ^ ((m >> 1) & 3);
                ldsm_x4(af, stage + m * 64 + up * 16);
#pragma unroll
                for (int nt = 0; nt < 8; nt++) {
                    mma16816(acc[mt][nt], af,
                             bf[nt >> 1][(nt & 1) * 2], bf[nt >> 1][(nt & 1) * 2 + 1]);
                }
            }
        }
        if (ch + 3 < nch) {
            og_load_chunk(sb + ((ch + 3) % OG_NST) * OG_STAGE,
                          A, B, m0, n0, (ch + 3) * 32, K, tid);
            CP_COMMIT();
        }
    }

    const int gr = lid >> 2;
    const int gc = (lid & 3) * 2;
#pragma unroll
    for (int nt = 0; nt < 8; nt++) {
        int col = n0 + wn0 + nt * 8 + gc;
        float bx = bias[col], by = bias[col + 1];
#pragma unroll
        for (int mt = 0; mt < 4; mt++) {
            int row = m0 + wm0 + mt * 16 + gr;
            *(float2*)&C[(size_t)row * ldc + col] =
                make_float2(acc[mt][nt][0] + bx, acc[mt][nt][1] + by);
            *(float2*)&C[(size_t)(row + 8) * ldc + col] =
                make_float2(acc[mt][nt][2] + bx, acc[mt][nt][3] + by);
        }
    }
}

// ---------------- launch ----------------
extern "C" void kernel_launch(void* const* d_in, const int* in_sizes, int n_in,
                              void* d_out, int out_size) {
    const unsigned int*  constraints = (const unsigned int*)d_in[0];
    const unsigned char* mask        = (const unsigned char*)d_in[1];
    const float* obj_e    = (const float*)d_in[2];
    const float* type_emb = (const float*)d_in[3];
    const float* dir_emb  = (const float*)d_in[4];
    const float* W1       = (const float*)d_in[5];
    const float* b1       = (const float*)d_in[6];
    const float* W2       = (const float*)d_in[7];
    const float* b2       = (const float*)d_in[8];
    float* out = (float*)d_out;

    float* pQR;
    __half *pOH, *pW1H, *pW1L, *pW2H, *pH16;
    cudaGetSymbolAddress((void**)&pQR,  g_QR);
    cudaGetSymbolAddress((void**)&pOH,  g_objH);
    cudaGetSymbolAddress((void**)&pW1H, g_W1H);
    cudaGetSymbolAddress((void**)&pW1L, g_W1L);
    cudaGetSymbolAddress((void**)&pW2H, g_W2H);
    cudaGetSymbolAddress((void**)&pH16, g_h16);

    cudaFuncSetAttribute(qr_gemm_kernel,
                         cudaFuncAttributeMaxDynamicSharedMemorySize,
                         QR_NST * QR_STAGE);
    cudaFuncSetAttribute(out_gemm_kernel,
                         cudaFuncAttributeMaxDynamicSharedMemorySize,
                         OG_NST * OG_STAGE);

    // 0) dtype detection
    detect_kernel<<<1, 32>>>(constraints, mask);
    // 1) TQ / DW (fp32 exact, tiny)
    emb_kernel<<<16, 256>>>(type_emb, dir_emb, W1);
    // 2) conversions
    conv_obj_kernel<<<(NB * D_MODEL) / 256, 256>>>(obj_e);
    w1t_kernel<<<(2048 * 512) / 256, 256>>>(W1);
    w2t_kernel<<<(512 * 1024) / 256, 256>>>(W2);
    // 3) QR = obj_e @ [W1_q | W1_r] * 64  (fp16 2-term HMMA)
    {
        dim3 grid(2048 / 128, NB / 128);   // (16, 64)
        qr_gemm_kernel<<<grid, 128, QR_NST * QR_STAGE>>>(
            pOH, pW1H, pW1L, pQR, D_MODEL, 2048);
    }
    // 4) h = relu(gather-sum + b1) -> single fp16
    build_h_kernel<<<SB, 256>>>(constraints, mask, b1);
    // 5) out = h @ W2 + b2  (fp16 1-term HMMA, tile 128x256, 4-stage)
    {
        dim3 grid(512 / 256, SB / 128);    // (2, 512)
        out_gemm_kernel<<<grid, 256, OG_NST * OG_STAGE>>>(
            pH16, pW2H, b2, out, H_DIM, 512);
    }
}